// round 10
// baseline (speedup 1.0000x reference)
#include <cuda_runtime.h>

#define BATCH 128
#define CH 1024

// Table config
#define G 32
#define GRANGE 6.0f
#define GSTEP (2.0f * GRANGE / (G - 1))

// GEMM config
#define G_NTILE 64
#define G_KSPLIT 16
#define G_KCHUNK (CH / G_KSPLIT)   // 64
#define KT 32
#define NTILES (CH / G_NTILE)      // 16
#define SHROW 36                   // h row stride (floats): 144B, 16B-aligned
#define SWROW 132                  // w stage row: 128 floats + 4 pad
#define BCH (BATCH * CH)

// Scratch (allocation-free rule: __device__ globals)
static __device__ float g_h[BCH];                  // 512 KB
static __device__ float g_wt[(CH / 2) * (2 * CH)]; // 4 MB: W taps, [kp][2o+p]
static __device__ float g_part[G_KSPLIT * BCH];    // 8 MB: split-K partials
static __device__ unsigned int g_cnt[NTILES];

typedef unsigned long long u64;
typedef unsigned int u32;

__device__ __forceinline__ float ex2f(float x) {
    float y;
    asm("ex2.approx.ftz.f32 %0, %1;" : "=f"(y) : "f"(x));
    return y;
}
__device__ __forceinline__ u64 fma2(u64 a, u64 b, u64 c) {
    u64 r; asm("fma.rn.f32x2 %0, %1, %2, %3;" : "=l"(r) : "l"(a), "l"(b), "l"(c)); return r;
}
__device__ __forceinline__ void upkf(float& lo, float& hi, u64 v) {
    asm("mov.b64 {%0,%1}, %2;" : "=f"(lo), "=f"(hi) : "l"(v));
}
__device__ __forceinline__ void cpa16(u32 dst, const float* src) {
    asm volatile("cp.async.ca.shared.global [%0], [%1], 16;" :: "r"(dst), "l"(src));
}
__device__ __forceinline__ void cpa_commit() {
    asm volatile("cp.async.commit_group;" ::: "memory");
}
template <int N> __device__ __forceinline__ void cpa_wait() {
    asm volatile("cp.async.wait_group %0;" :: "n"(N) : "memory");
}

// ---------------------------------------------------------------------------
// Kernel 1: table + Hermite interp + W compaction.  128 CTAs x 256 threads.
// ---------------------------------------------------------------------------
__global__ __launch_bounds__(256) void fused_cross(
    const float* __restrict__ visual, const float* __restrict__ tactile,
    const float* __restrict__ conv_w)
{
    __shared__ __align__(16) float vl[CH];
    __shared__ __align__(16) float vl2[CH];
    __shared__ float sden[G][8], snum[G][8], sm2[G][8];
    __shared__ float tab[G], der[G];

    const int b = blockIdx.x;
    const float LOG2E = 1.4426950408889634f;
    const float LN2   = 0.6931471805599453f;

    if (b == 0 && threadIdx.x < NTILES) g_cnt[threadIdx.x] = 0;

    // vl fill first so table math isn't gated on the compaction stream
    const float* vb = visual + b * CH;
#pragma unroll
    for (int k = 0; k < 4; k++) {
        int idx = threadIdx.x + k * 256;
        float v = vb[idx] * LOG2E;
        vl[idx] = v;
        vl2[idx] = v * v;
    }

    // ---- W compaction: stride-9 center-tap gather -> dense [kp][2o+p] ----
    {
        const int wid_g = b * 8 + (threadIdx.x >> 5);   // 0..1023
        const int lane  = threadIdx.x & 31;
        const int o     = (wid_g & 31) * 32 + lane;     // 0..1023
        const int kpb   = (wid_g >> 5) * 16;            // 0..496
        const float* wsrc = conv_w + o * (CH * 9) + 4;  // + k*9
#pragma unroll
        for (int q = 0; q < 16; q++) {
            int kp = kpb + q;
            float a0 = __ldcg(&wsrc[(2 * kp) * 9]);
            float a1 = __ldcg(&wsrc[(2 * kp + 1) * 9]);
            *(float2*)&g_wt[kp * (2 * CH) + 2 * o] = make_float2(a0, a1);
        }
    }
    __syncthreads();

    // ---- table: G=32 points of g(s), g'(s), 8 threads/point ----
    const int p  = threadIdx.x >> 3;
    const int h8 = threadIdx.x & 7;
    const float s = -GRANGE + GSTEP * (float)p;

    float den0 = 0.f, den1 = 0.f, num0 = 0.f, num1 = 0.f, m20 = 0.f, m21 = 0.f;
    const float4* v4 = reinterpret_cast<const float4*>(vl);
    const float4* w4 = reinterpret_cast<const float4*>(vl2);
#pragma unroll 4
    for (int j = 0; j < CH / 32; j++) {
        float4 v = v4[j * 8 + h8];
        float4 w = w4[j * 8 + h8];
        float e0 = ex2f(s * v.x);
        float e1 = ex2f(s * v.y);
        float e2 = ex2f(s * v.z);
        float e3 = ex2f(s * v.w);
        den0 += e0 + e2;
        den1 += e1 + e3;
        num0 = fmaf(e0, v.x, num0);
        num1 = fmaf(e1, v.y, num1);
        num0 = fmaf(e2, v.z, num0);
        num1 = fmaf(e3, v.w, num1);
        m20 = fmaf(e0, w.x, m20);
        m21 = fmaf(e1, w.y, m21);
        m20 = fmaf(e2, w.z, m20);
        m21 = fmaf(e3, w.w, m21);
    }
    sden[p][h8] = den0 + den1;
    snum[p][h8] = num0 + num1;
    sm2[p][h8]  = m20 + m21;
    __syncthreads();

    if (threadIdx.x < G) {
        int q = threadIdx.x;
        float den = 0.f, num = 0.f, m2 = 0.f;
#pragma unroll
        for (int r = 0; r < 8; r++) { den += sden[q][r]; num += snum[q][r]; m2 += sm2[q][r]; }
        float inv = __fdividef(1.0f, den);
        float nd = num * inv;
        tab[q] = nd * LN2;
        der[q] = (LN2 * LN2) * (m2 * inv - nd * nd) * GSTEP;
    }
    __syncthreads();

    // ---- Hermite interp -> h ----
#pragma unroll
    for (int k = 0; k < 4; k++) {
        int i = threadIdx.x + k * 256;
        float t = tactile[b * CH + i];
        float x = (t + GRANGE) * (1.0f / GSTEP);
        x = fminf(fmaxf(x, 0.0f), (float)(G - 1) - 1e-3f);
        int i1 = (int)x;
        float u = x - (float)i1;
        float p1 = tab[i1], p2 = tab[i1 + 1];
        float m1 = der[i1], m2 = der[i1 + 1];
        float c2 = 3.0f * (p2 - p1) - 2.0f * m1 - m2;
        float c3 = 2.0f * (p1 - p2) + m1 + m2;
        float crossed = ((c3 * u + c2) * u + m1) * u + p1;
        g_h[b * CH + i] = vl[i] * LN2 + crossed;
    }
}

// ---------------------------------------------------------------------------
// Kernel 2: split-K GEMM, NO atomics. Partials -> g_part[kz] via STG.128.
// Last k-split CTA per n-tile (counter) reduces 16 partials + bias/BN/LeakyReLU.
// grid = 16 n-tiles x 16 k-splits, 256 threads, 2 CTAs/SM.
// Thread tile 8b x 4o with o = 4*tx + oi (contiguous -> LDS.128 / STG.128).
// ---------------------------------------------------------------------------
__global__ __launch_bounds__(256, 2) void gemm_final(
    const float* __restrict__ cb, const float* __restrict__ gamma,
    const float* __restrict__ beta, const float* __restrict__ mean,
    const float* __restrict__ var, float* __restrict__ out)
{
    __shared__ __align__(16) float sh[BATCH * SHROW];       // 18.4 KB
    __shared__ __align__(16) float sw[2][(KT / 2) * SWROW]; // 16.9 KB
    __shared__ float sA[G_NTILE], sC[G_NTILE];
    __shared__ int s_done;

    const int nb = blockIdx.x & (NTILES - 1);
    const int kz = blockIdx.x >> 4;
    const int nbase = nb * G_NTILE;
    const int kbase = kz * G_KCHUNK;
    const int kp0 = kbase >> 1;

    const int t = threadIdx.x;
    const int tx = t & 15;             // o group: o = 4*tx + oi
    const int ty = t >> 4;             // b lane: b = ty + 16*bi

    const u32 sh_base = (u32)__cvta_generic_to_shared(sh);
    const u32 sw_base0 = (u32)__cvta_generic_to_shared(&sw[0][0]);
    const u32 sw_base1 = (u32)__cvta_generic_to_shared(&sw[1][0]);

    // ---- issue stage0: h + W ----
#pragma unroll
    for (int it = 0; it < 4; it++) {
        int e = t + it * 256;
        int r = e >> 3, c4 = (e & 7) * 4;
        cpa16(sh_base + (r * SHROW + c4) * 4, &g_h[r * CH + kbase + c4]);
    }
#pragma unroll
    for (int it = 0; it < 2; it++) {
        int e = t + it * 256;
        int row = e >> 5, c4 = (e & 31) * 4;
        cpa16(sw_base0 + (row * SWROW + c4) * 4,
              &g_wt[(kp0 + row) * (2 * CH) + nbase * 2 + c4]);
    }
    cpa_commit();
    // ---- prefetch stage1 W ----
#pragma unroll
    for (int it = 0; it < 2; it++) {
        int e = t + it * 256;
        int row = e >> 5, c4 = (e & 31) * 4;
        cpa16(sw_base1 + (row * SWROW + c4) * 4,
              &g_wt[(kp0 + 16 + row) * (2 * CH) + nbase * 2 + c4]);
    }
    cpa_commit();

    u64 acc[8][4] = {};

    cpa_wait<1>();
    __syncthreads();

    // ---- compute stage 0 ----
#pragma unroll 4
    for (int kp = 0; kp < KT / 2; kp++) {
        u64 hb[8], wo[4];
#pragma unroll
        for (int bi = 0; bi < 8; bi++)
            hb[bi] = *(const u64*)&sh[(ty + 16 * bi) * SHROW + kp * 2];
        // 4 consecutive k-paired W values for o = 4tx..4tx+3 (2x LDS.128)
        *(float4*)&wo[0] = *(const float4*)&sw[0][kp * SWROW + 8 * tx];
        *(float4*)&wo[2] = *(const float4*)&sw[0][kp * SWROW + 8 * tx + 4];
#pragma unroll
        for (int bi = 0; bi < 8; bi++)
#pragma unroll
            for (int oi = 0; oi < 4; oi++)
                acc[bi][oi] = fma2(hb[bi], wo[oi], acc[bi][oi]);
    }
    __syncthreads();

    // ---- refill h for stage 1 ----
#pragma unroll
    for (int it = 0; it < 4; it++) {
        int e = t + it * 256;
        int r = e >> 3, c4 = (e & 7) * 4;
        cpa16(sh_base + (r * SHROW + c4) * 4, &g_h[r * CH + kbase + KT + c4]);
    }
    cpa_commit();
    cpa_wait<0>();
    __syncthreads();

    // ---- compute stage 1 ----
#pragma unroll 4
    for (int kp = 0; kp < KT / 2; kp++) {
        u64 hb[8], wo[4];
#pragma unroll
        for (int bi = 0; bi < 8; bi++)
            hb[bi] = *(const u64*)&sh[(ty + 16 * bi) * SHROW + kp * 2];
        *(float4*)&wo[0] = *(const float4*)&sw[1][kp * SWROW + 8 * tx];
        *(float4*)&wo[2] = *(const float4*)&sw[1][kp * SWROW + 8 * tx + 4];
#pragma unroll
        for (int bi = 0; bi < 8; bi++)
#pragma unroll
            for (int oi = 0; oi < 4; oi++)
                acc[bi][oi] = fma2(hb[bi], wo[oi], acc[bi][oi]);
    }

    // ---- partial store (plain STG.128, no atomics) ----
    float* pp = g_part + kz * BCH;
#pragma unroll
    for (int bi = 0; bi < 8; bi++) {
        int b = ty + 16 * bi;
        float4 r;
        float lo, hi;
        upkf(lo, hi, acc[bi][0]); r.x = lo + hi;
        upkf(lo, hi, acc[bi][1]); r.y = lo + hi;
        upkf(lo, hi, acc[bi][2]); r.z = lo + hi;
        upkf(lo, hi, acc[bi][3]); r.w = lo + hi;
        *(float4*)&pp[b * CH + nbase + 4 * tx] = r;
    }

    // ---- finalize: last k-split CTA per n-tile reduces + epilogue ----
    __threadfence();
    __syncthreads();
    if (t == 0) {
        unsigned int old = atomicAdd(&g_cnt[nb], 1u);
        s_done = (old == G_KSPLIT - 1) ? 1 : 0;
    }
    __syncthreads();
    if (!s_done) return;

    __threadfence();
    if (t < G_NTILE) {
        int o = nbase + t;
        float A = gamma[o] * rsqrtf(var[o] + 1e-5f);
        sA[t] = A;
        sC[t] = (cb[o] - mean[o]) * A + beta[o];
    }
    __syncthreads();

#pragma unroll
    for (int it = 0; it < 8; it++) {
        int e = t + it * 256;
        int b = e >> 4;
        int oq = (e & 15) * 4;
        int off = b * CH + nbase + oq;
        float4 s0 = __ldcg((const float4*)&g_part[off]);
        float4 s1 = __ldcg((const float4*)&g_part[BCH + off]);
#pragma unroll
        for (int kz2 = 2; kz2 < G_KSPLIT; kz2 += 2) {
            float4 a = __ldcg((const float4*)&g_part[kz2 * BCH + off]);
            float4 c = __ldcg((const float4*)&g_part[(kz2 + 1) * BCH + off]);
            s0.x += a.x; s0.y += a.y; s0.z += a.z; s0.w += a.w;
            s1.x += c.x; s1.y += c.y; s1.z += c.z; s1.w += c.w;
        }
        float4 r;
        float v;
        v = (s0.x + s1.x) * sA[oq + 0] + sC[oq + 0]; r.x = v > 0.f ? v : 0.1f * v;
        v = (s0.y + s1.y) * sA[oq + 1] + sC[oq + 1]; r.y = v > 0.f ? v : 0.1f * v;
        v = (s0.z + s1.z) * sA[oq + 2] + sC[oq + 2]; r.z = v > 0.f ? v : 0.1f * v;
        v = (s0.w + s1.w) * sA[oq + 3] + sC[oq + 3]; r.w = v > 0.f ? v : 0.1f * v;
        *(float4*)&out[off] = r;
    }
}

extern "C" void kernel_launch(void* const* d_in, const int* in_sizes, int n_in,
                              void* d_out, int out_size)
{
    const float* visual  = (const float*)d_in[0];
    const float* tactile = (const float*)d_in[1];
    const float* conv_w  = (const float*)d_in[2];
    const float* conv_b  = (const float*)d_in[3];
    const float* gamma   = (const float*)d_in[4];
    const float* beta    = (const float*)d_in[5];
    const float* mean    = (const float*)d_in[6];
    const float* var     = (const float*)d_in[7];
    float* out = (float*)d_out;

    fused_cross<<<BATCH, 256>>>(visual, tactile, conv_w);
    gemm_final<<<NTILES * G_KSPLIT, 256>>>(conv_b, gamma, beta, mean, var, out);
}

// round 12
// speedup vs baseline: 1.8171x; 1.8171x over previous
#include <cuda_runtime.h>

#define BATCH 128
#define CH 1024

// Table config
#define G 32
#define GRANGE 6.0f
#define GSTEP (2.0f * GRANGE / (G - 1))

// GEMM config
#define G_NTILE 64
#define G_KSPLIT 16
#define G_KCHUNK (CH / G_KSPLIT)   // 64
#define KT 32
#define NTILES (CH / G_NTILE)      // 16
#define SHROW 36                   // h row stride (floats): 144B, 16B-aligned
#define SWROW 34                   // w row stride (floats): 8B-aligned, bank-rotated

// Scratch (allocation-free rule: __device__ globals)
static __device__ float g_h[BATCH * CH];     // 512 KB
static __device__ float g_acc[BATCH * CH];   // 512 KB
static __device__ unsigned int g_cnt[NTILES];

typedef unsigned int u32;

__device__ __forceinline__ float ex2f(float x) {
    float y;
    asm("ex2.approx.ftz.f32 %0, %1;" : "=f"(y) : "f"(x));
    return y;
}
__device__ __forceinline__ void cpa4(u32 dst, const float* src) {
    asm volatile("cp.async.ca.shared.global [%0], [%1], 4;" :: "r"(dst), "l"(src));
}
__device__ __forceinline__ void cpa16(u32 dst, const float* src) {
    asm volatile("cp.async.ca.shared.global [%0], [%1], 16;" :: "r"(dst), "l"(src));
}
__device__ __forceinline__ void cpa_commit() {
    asm volatile("cp.async.commit_group;" ::: "memory");
}
template <int N> __device__ __forceinline__ void cpa_wait() {
    asm volatile("cp.async.wait_group %0;" :: "n"(N) : "memory");
}

// ---------------------------------------------------------------------------
// Kernel 1: fused table + Hermite interp (R8-proven). 128 CTAs x 256 threads.
// Zeroes g_acc for the GEMM's atomic accumulation; CTA 0 zeroes counters.
// ---------------------------------------------------------------------------
__global__ __launch_bounds__(256) void fused_cross(
    const float* __restrict__ visual, const float* __restrict__ tactile)
{
    __shared__ __align__(16) float vl[CH];
    __shared__ __align__(16) float vl2[CH];
    __shared__ float sden[G][8], snum[G][8], sm2[G][8];
    __shared__ float tab[G], der[G];

    const int b = blockIdx.x;
    const float LOG2E = 1.4426950408889634f;
    const float LN2   = 0.6931471805599453f;

    if (b == 0 && threadIdx.x < NTILES) g_cnt[threadIdx.x] = 0;

    const float* vb = visual + b * CH;
#pragma unroll
    for (int k = 0; k < 4; k++) {
        int idx = threadIdx.x + k * 256;
        float v = vb[idx] * LOG2E;
        vl[idx] = v;
        vl2[idx] = v * v;
    }
    __syncthreads();

    // ---- table: G=32 points of g(s), g'(s), 8 threads/point ----
    const int p  = threadIdx.x >> 3;
    const int h8 = threadIdx.x & 7;
    const float s = -GRANGE + GSTEP * (float)p;

    float den0 = 0.f, den1 = 0.f, num0 = 0.f, num1 = 0.f, m20 = 0.f, m21 = 0.f;
    const float4* v4 = reinterpret_cast<const float4*>(vl);
    const float4* w4 = reinterpret_cast<const float4*>(vl2);
#pragma unroll 4
    for (int j = 0; j < CH / 32; j++) {
        float4 v = v4[j * 8 + h8];
        float4 w = w4[j * 8 + h8];
        float e0 = ex2f(s * v.x);
        float e1 = ex2f(s * v.y);
        float e2 = ex2f(s * v.z);
        float e3 = ex2f(s * v.w);
        den0 += e0 + e2;
        den1 += e1 + e3;
        num0 = fmaf(e0, v.x, num0);
        num1 = fmaf(e1, v.y, num1);
        num0 = fmaf(e2, v.z, num0);
        num1 = fmaf(e3, v.w, num1);
        m20 = fmaf(e0, w.x, m20);
        m21 = fmaf(e1, w.y, m21);
        m20 = fmaf(e2, w.z, m20);
        m21 = fmaf(e3, w.w, m21);
    }
    sden[p][h8] = den0 + den1;
    snum[p][h8] = num0 + num1;
    sm2[p][h8]  = m20 + m21;
    __syncthreads();

    if (threadIdx.x < G) {
        int q = threadIdx.x;
        float den = 0.f, num = 0.f, m2 = 0.f;
#pragma unroll
        for (int r = 0; r < 8; r++) { den += sden[q][r]; num += snum[q][r]; m2 += sm2[q][r]; }
        float inv = __fdividef(1.0f, den);
        float nd = num * inv;
        tab[q] = nd * LN2;
        der[q] = (LN2 * LN2) * (m2 * inv - nd * nd) * GSTEP;
    }
    __syncthreads();

    // ---- Hermite interp -> h; zero g_acc ----
#pragma unroll
    for (int k = 0; k < 4; k++) {
        int i = threadIdx.x + k * 256;
        float t = tactile[b * CH + i];
        float x = (t + GRANGE) * (1.0f / GSTEP);
        x = fminf(fmaxf(x, 0.0f), (float)(G - 1) - 1e-3f);
        int i1 = (int)x;
        float u = x - (float)i1;
        float p1 = tab[i1], p2 = tab[i1 + 1];
        float m1 = der[i1], m2 = der[i1 + 1];
        float c2 = 3.0f * (p2 - p1) - 2.0f * m1 - m2;
        float c3 = 2.0f * (p1 - p2) + m1 + m2;
        float crossed = ((c3 * u + c2) * u + m1) * u + p1;
        g_h[b * CH + i] = vl[i] * LN2 + crossed;
        g_acc[b * CH + i] = 0.f;
    }
}

// ---------------------------------------------------------------------------
// Kernel 2: split-K GEMM + finalize. SCALAR FFMA inner loop (no f32x2 — the
// sm_103 target emulates it). cp.async pipelined stride-9 W gather with
// lanes->k (9 lines/warp). grid = 16 n-tiles x 16 k-splits, 256 threads,
// 2 CTAs/SM. Thread tile 8b x 4o with even/odd-k accumulators.
// ---------------------------------------------------------------------------
__global__ __launch_bounds__(256, 2) void gemm_final(
    const float* __restrict__ conv_w,
    const float* __restrict__ cb, const float* __restrict__ gamma,
    const float* __restrict__ beta, const float* __restrict__ mean,
    const float* __restrict__ var, float* __restrict__ out)
{
    __shared__ __align__(16) float sh[BATCH * SHROW];          // 18.4 KB
    __shared__ __align__(16) float sw[2][G_NTILE * SWROW];     // 17.4 KB
    __shared__ float sA[G_NTILE], sC[G_NTILE];
    __shared__ int s_done;

    const int nb = blockIdx.x & (NTILES - 1);
    const int kz = blockIdx.x >> 4;
    const int nbase = nb * G_NTILE;
    const int kbase = kz * G_KCHUNK;

    const int t = threadIdx.x;
    const int tx = t & 15;             // o lane: o = tx + 16*oi
    const int ty = t >> 4;             // b lane: b = ty + 16*bi
    const int lane = t & 31;           // k within W gather warp
    const int wrp  = t >> 5;

    const u32 sh_base = (u32)__cvta_generic_to_shared(sh);
    const u32 sw_base0 = (u32)__cvta_generic_to_shared(&sw[0][0]);
    const u32 sw_base1 = (u32)__cvta_generic_to_shared(&sw[1][0]);

    // ---- issue stage0: h + W ----
#pragma unroll
    for (int it = 0; it < 4; it++) {
        int e = t + it * 256;
        int r = e >> 3, c4 = (e & 7) * 4;
        cpa16(sh_base + (r * SHROW + c4) * 4, &g_h[r * CH + kbase + c4]);
    }
#pragma unroll
    for (int it = 0; it < 8; it++) {
        int o = wrp + 8 * it;          // lanes sweep k -> 9-line span per warp
        cpa4(sw_base0 + (o * SWROW + lane) * 4,
             &conv_w[((nbase + o) * CH + kbase + lane) * 9 + 4]);
    }
    cpa_commit();
    // ---- prefetch stage1 W (hides behind compute0) ----
#pragma unroll
    for (int it = 0; it < 8; it++) {
        int o = wrp + 8 * it;
        cpa4(sw_base1 + (o * SWROW + lane) * 4,
             &conv_w[((nbase + o) * CH + kbase + KT + lane) * 9 + 4]);
    }
    cpa_commit();

    float accE[8][4] = {};
    float accO[8][4] = {};

    cpa_wait<1>();                     // stage0 ready
    __syncthreads();

    // ---- compute stage 0 (scalar FFMA) ----
#pragma unroll 4
    for (int kp = 0; kp < KT / 2; kp++) {
        float2 hb[8], wo[4];
#pragma unroll
        for (int bi = 0; bi < 8; bi++)
            hb[bi] = *(const float2*)&sh[(ty + 16 * bi) * SHROW + kp * 2];
#pragma unroll
        for (int oi = 0; oi < 4; oi++)
            wo[oi] = *(const float2*)&sw[0][(tx + 16 * oi) * SWROW + kp * 2];
#pragma unroll
        for (int bi = 0; bi < 8; bi++)
#pragma unroll
            for (int oi = 0; oi < 4; oi++) {
                accE[bi][oi] = fmaf(hb[bi].x, wo[oi].x, accE[bi][oi]);
                accO[bi][oi] = fmaf(hb[bi].y, wo[oi].y, accO[bi][oi]);
            }
    }
    __syncthreads();                   // done reading sh

    // ---- refill h for stage 1 ----
#pragma unroll
    for (int it = 0; it < 4; it++) {
        int e = t + it * 256;
        int r = e >> 3, c4 = (e & 7) * 4;
        cpa16(sh_base + (r * SHROW + c4) * 4, &g_h[r * CH + kbase + KT + c4]);
    }
    cpa_commit();
    cpa_wait<0>();                     // stage1 W + h ready
    __syncthreads();

    // ---- compute stage 1 ----
#pragma unroll 4
    for (int kp = 0; kp < KT / 2; kp++) {
        float2 hb[8], wo[4];
#pragma unroll
        for (int bi = 0; bi < 8; bi++)
            hb[bi] = *(const float2*)&sh[(ty + 16 * bi) * SHROW + kp * 2];
#pragma unroll
        for (int oi = 0; oi < 4; oi++)
            wo[oi] = *(const float2*)&sw[1][(tx + 16 * oi) * SWROW + kp * 2];
#pragma unroll
        for (int bi = 0; bi < 8; bi++)
#pragma unroll
            for (int oi = 0; oi < 4; oi++) {
                accE[bi][oi] = fmaf(hb[bi].x, wo[oi].x, accE[bi][oi]);
                accO[bi][oi] = fmaf(hb[bi].y, wo[oi].y, accO[bi][oi]);
            }
    }

    // ---- partial accumulate (spread-address atomics) ----
#pragma unroll
    for (int bi = 0; bi < 8; bi++) {
        int b = ty + 16 * bi;
#pragma unroll
        for (int oi = 0; oi < 4; oi++)
            atomicAdd(&g_acc[b * CH + nbase + tx + 16 * oi], accE[bi][oi] + accO[bi][oi]);
    }

    // ---- finalize: last k-split CTA per n-tile ----
    __threadfence();
    __syncthreads();
    if (t == 0) {
        unsigned int old = atomicAdd(&g_cnt[nb], 1u);
        s_done = (old == G_KSPLIT - 1) ? 1 : 0;
    }
    __syncthreads();
    if (!s_done) return;

    __threadfence();
    if (t < G_NTILE) {
        int o = nbase + t;
        float A = gamma[o] * rsqrtf(var[o] + 1e-5f);
        sA[t] = A;
        sC[t] = (cb[o] - mean[o]) * A + beta[o];
    }
    __syncthreads();

#pragma unroll
    for (int it = 0; it < 8; it++) {
        int e = t + it * 256;
        int b = e >> 4;
        int oq = (e & 15) * 4;
        int off = b * CH + nbase + oq;
        float4 sv = __ldcg((const float4*)&g_acc[off]);
        float4 r;
        float v;
        v = sv.x * sA[oq + 0] + sC[oq + 0]; r.x = v > 0.f ? v : 0.1f * v;
        v = sv.y * sA[oq + 1] + sC[oq + 1]; r.y = v > 0.f ? v : 0.1f * v;
        v = sv.z * sA[oq + 2] + sC[oq + 2]; r.z = v > 0.f ? v : 0.1f * v;
        v = sv.w * sA[oq + 3] + sC[oq + 3]; r.w = v > 0.f ? v : 0.1f * v;
        *(float4*)&out[off] = r;
    }
}

extern "C" void kernel_launch(void* const* d_in, const int* in_sizes, int n_in,
                              void* d_out, int out_size)
{
    const float* visual  = (const float*)d_in[0];
    const float* tactile = (const float*)d_in[1];
    const float* conv_w  = (const float*)d_in[2];
    const float* conv_b  = (const float*)d_in[3];
    const float* gamma   = (const float*)d_in[4];
    const float* beta    = (const float*)d_in[5];
    const float* mean    = (const float*)d_in[6];
    const float* var     = (const float*)d_in[7];
    float* out = (float*)d_out;

    fused_cross<<<BATCH, 256>>>(visual, tactile);
    gemm_final<<<NTILES * G_KSPLIT, 256>>>(conv_w, conv_b, gamma, beta, mean, var, out);
}